// round 15
// baseline (speedup 1.0000x reference)
#include <cuda_runtime.h>
#include <cuda_bf16.h>
#include <cstdint>

// ---------------------------------------------------------------------------
// SPMoEAdaptor: out = moe_b(moe_a(x)) + x
//   moe(x) = sum_e softmax(x@Wg)[:,e] * ((x - b_e) @ W_e)
// R14: paired-warp N-split. Each 32-row unit is computed by TWO warps, each
// owning 32 output cols -> acc is 32 regs (not 64), letting 512-thr CTAs run
// at <=128 regs WITHOUT spills (R6 failed with 64-reg acc): 16 warps/SM
// (4/SMSP, +33%) to cover the ~2.6k-cycle serial window per unit. Layer B
// needs full h: pair exchanges bf16 halves via a smem h-buffer (stride 144 =
// conflict-free) guarded by named pair-barriers; pack rounding identical to
// the old register repack -> bit-identical output. Pair shares one cp.async
// x-stage and one work-steal (leader broadcasts). bf16 HMMA throughout.
// ---------------------------------------------------------------------------

namespace {
constexpr int SM_W     = 0;             // 64KB bf16 weights, both layers (n-major)
constexpr int SM_WGA   = 65536;         // 64 x float4 (w_gate_a as [d][e])
constexpr int SM_WGB   = 66560;
constexpr int SM_CA    = 67584;         // 64 x float4 (c_a as [f][e])
constexpr int SM_CB    = 68608;
constexpr int SM_CTL   = 69632;         // 8 pairs x 8B steal slots
constexpr int SM_H     = 70656;         // 8 pairs x 32x144B bf16 h-buffer
constexpr int H_ROW    = 144;           // stride/4 == 36 -> bank = 4*row+colw (conflict-free)
constexpr int H_PAIR   = 32 * H_ROW;    // 4608
constexpr int SM_STAGE = SM_H + 8 * H_PAIR;       // 107520
constexpr int STAGE_ROW  = 288;
constexpr int STAGE_PAIR = 32 * STAGE_ROW;        // 9216
constexpr int SMEM_TOTAL = SM_STAGE + 8 * STAGE_PAIR;  // 181248

constexpr int GRID = 148;               // 1 CTA per SM, 512 threads
}

// device-global scratch (allocation-free rule)
__device__ __align__(16) __nv_bfloat16 g_wswz[2][64 * 256];
__device__ __align__(16) float g_c[2][64 * 4];
__device__ unsigned g_unit_ctr;
__device__ int g_cflag;                 // 1 iff all c == 0 (fast path)

// ------------------------------- helpers ----------------------------------

__device__ __forceinline__ uint32_t smem_u32(const void* p) {
    uint32_t a;
    asm("{ .reg .u64 t; cvta.to.shared.u64 t, %1; cvt.u32.u64 %0, t; }" : "=r"(a) : "l"(p));
    return a;
}

__device__ __forceinline__ void ldsm_x4(uint32_t* r, uint32_t addr) {
    asm volatile("ldmatrix.sync.aligned.m8n8.x4.shared.b16 {%0,%1,%2,%3}, [%4];"
                 : "=r"(r[0]), "=r"(r[1]), "=r"(r[2]), "=r"(r[3]) : "r"(addr));
}

__device__ __forceinline__ void mma_bf16(float* d, const uint32_t* a,
                                         uint32_t b0, uint32_t b1) {
    asm volatile("mma.sync.aligned.m16n8k16.row.col.f32.bf16.bf16.f32 "
                 "{%0,%1,%2,%3}, {%4,%5,%6,%7}, {%8,%9}, {%0,%1,%2,%3};"
                 : "+f"(d[0]), "+f"(d[1]), "+f"(d[2]), "+f"(d[3])
                 : "r"(a[0]), "r"(a[1]), "r"(a[2]), "r"(a[3]), "r"(b0), "r"(b1));
}

__device__ __forceinline__ uint32_t pack_bf2(float lo, float hi) {
    __nv_bfloat162 t = __floats2bfloat162_rn(lo, hi);
    return *reinterpret_cast<uint32_t*>(&t);
}

__device__ __forceinline__ uint32_t bf2bcast(float v) { return pack_bf2(v, v); }

__device__ __forceinline__ uint32_t hmul2u(uint32_t a, uint32_t b) {
    __nv_bfloat162 r = __hmul2(*reinterpret_cast<__nv_bfloat162*>(&a),
                               *reinterpret_cast<__nv_bfloat162*>(&b));
    return *reinterpret_cast<uint32_t*>(&r);
}

__device__ __forceinline__ float dot4(float4 a, float4 b) {
    return a.x * b.x + a.y * b.y + a.z * b.z + a.w * b.w;
}

__device__ __forceinline__ float4 softmax4(float4 l) {
    float mx = fmaxf(fmaxf(l.x, l.y), fmaxf(l.z, l.w));
    float e0 = __expf(l.x - mx), e1 = __expf(l.y - mx),
          e2 = __expf(l.z - mx), e3 = __expf(l.w - mx);
    float inv = 1.f / (e0 + e1 + e2 + e3);
    return make_float4(e0 * inv, e1 * inv, e2 * inv, e3 * inv);
}

__device__ __forceinline__ void barpair(int barid) {
    asm volatile("bar.sync %0, 64;" :: "r"(barid) : "memory");
}

__device__ __forceinline__ void st_ctl(uint32_t addr, unsigned v) {
    asm volatile("st.shared.u32 [%0], %1;" :: "r"(addr), "r"(v) : "memory");
}
__device__ __forceinline__ unsigned ld_ctl(uint32_t addr) {
    unsigned v;
    asm volatile("ld.shared.u32 %0, [%1];" : "=r"(v) : "r"(addr) : "memory");
    return v;
}

// each warp copies its 16 rows of unit u into the PAIR stage
__device__ __forceinline__ void issue_stage(const float* __restrict__ x, unsigned u,
                                            uint32_t stage_u, int half, int lane) {
    const float* src = x + (size_t)u * 32 * 64 + (size_t)half * 16 * 64;
    const int hl = lane >> 4;
    const int ch = lane & 15;
    #pragma unroll
    for (int i = 0; i < 8; i++) {
        int row = 2 * i + hl;                       // 0..15 within this half
        uint32_t dst = stage_u + (uint32_t)((half * 16 + row) * STAGE_ROW + ch * 16);
        const float* s = src + row * 64 + ch * 4;
        asm volatile("cp.async.cg.shared.global [%0], [%1], 16;" :: "r"(dst), "l"(s));
    }
    asm volatile("cp.async.commit_group;" ::: "memory");
}

__device__ __forceinline__ void stage_wait() {
    asm volatile("cp.async.wait_group 0;" ::: "memory");
    __syncwarp();
}

// half-width MoE GEMM layer: this warp's 2 np-blocks only.
// wbase_half = SM_W base (+32768 for layer B) + half*16384.
__device__ __forceinline__ void run_layer_half(float acc[2][4][4],
                                               const uint32_t xf[2][4][4],
                                               const uint32_t g2[4][2][2],
                                               uint32_t wbase_half, int lane) {
    const int l7 = lane & 7;
    const uint32_t lane_row = (uint32_t)(((lane >> 4) & 1) * 8 + l7);
    const uint32_t kh = (uint32_t)((lane >> 3) & 1);
    const uint32_t lane_base = wbase_half + lane_row * 512u;
    #pragma unroll
    for (int e = 0; e < 4; e++) {
        #pragma unroll
        for (int kt = 0; kt < 4; kt++) {
            const uint32_t c0 = (uint32_t)(e * 8 + kt * 2) + kh;
            const uint32_t coff = ((c0 ^ (uint32_t)l7) << 4);
            uint32_t bb[2][4];
            ldsm_x4(bb[0], lane_base + coff);
            ldsm_x4(bb[1], lane_base + 8192u + coff);
            uint32_t a[2][4];
            #pragma unroll
            for (int m = 0; m < 2; m++) {
                a[m][0] = hmul2u(xf[m][kt][0], g2[e][m][0]);
                a[m][1] = hmul2u(xf[m][kt][1], g2[e][m][1]);
                a[m][2] = hmul2u(xf[m][kt][2], g2[e][m][0]);
                a[m][3] = hmul2u(xf[m][kt][3], g2[e][m][1]);
            }
            #pragma unroll
            for (int np = 0; np < 2; np++) {
                mma_bf16(acc[0][2 * np],     a[0], bb[np][0], bb[np][1]);
                mma_bf16(acc[0][2 * np + 1], a[0], bb[np][2], bb[np][3]);
                mma_bf16(acc[1][2 * np],     a[1], bb[np][0], bb[np][1]);
                mma_bf16(acc[1][2 * np + 1], a[1], bb[np][2], bb[np][3]);
            }
        }
    }
}

// gates: tensor-core logits -> softmax -> bcast pairs (g2). Optionally also
// float4 gate vectors (gf != nullptr) for the general-path bias folds.
__device__ __forceinline__ void gates_core(const uint32_t xf[4][4],
                                           const uint32_t* wg0,
                                           const uint32_t* wg1,
                                           int ql, uint32_t g2[4][2],
                                           float4* gf) {
    float l[4]  = {0.f, 0.f, 0.f, 0.f};
    float l2[4] = {0.f, 0.f, 0.f, 0.f};
    mma_bf16(l,  xf[0], wg0[0], wg1[0]);
    mma_bf16(l2, xf[1], wg0[1], wg1[1]);
    mma_bf16(l,  xf[2], wg0[2], wg1[2]);
    mma_bf16(l2, xf[3], wg0[3], wg1[3]);
    l[0] += l2[0]; l[1] += l2[1]; l[2] += l2[2]; l[3] += l2[3];
    float r0 = __shfl_xor_sync(0xffffffffu, l[0], 1);
    float r1 = __shfl_xor_sync(0xffffffffu, l[1], 1);
    float r2 = __shfl_xor_sync(0xffffffffu, l[2], 1);
    float r3 = __shfl_xor_sync(0xffffffffu, l[3], 1);
    bool even = (ql & 1) == 0;
    float4 La = even ? make_float4(l[0], l[1], r0, r1)
                     : make_float4(r0, r1, l[0], l[1]);
    float4 Lb = even ? make_float4(l[2], l[3], r2, r3)
                     : make_float4(r2, r3, l[2], l[3]);
    float4 ga = softmax4(La);
    float4 gb = softmax4(Lb);
    if (gf) { gf[0] = ga; gf[1] = gb; }
    g2[0][0] = bf2bcast(ga.x); g2[1][0] = bf2bcast(ga.y);
    g2[2][0] = bf2bcast(ga.z); g2[3][0] = bf2bcast(ga.w);
    g2[0][1] = bf2bcast(gb.x); g2[1][1] = bf2bcast(gb.y);
    g2[2][1] = bf2bcast(gb.z); g2[3][1] = bf2bcast(gb.w);
}

// build Wg B-fragments from smem (done per-use to cap register liveness)
__device__ __forceinline__ void build_wg(const float* WGf, int ql, int qr,
                                         uint32_t* w0, uint32_t* w1) {
    const int e4 = qr & 3;
    #pragma unroll
    for (int kt = 0; kt < 4; kt++) {
        int d0 = kt * 16 + 2 * ql;
        w0[kt] = pack_bf2(WGf[d0 * 4 + e4],       WGf[(d0 + 1) * 4 + e4]);
        w1[kt] = pack_bf2(WGf[(d0 + 8) * 4 + e4], WGf[(d0 + 9) * 4 + e4]);
    }
}

// ------------------------------- prep kernel ------------------------------

__global__ void prep_kernel(const float* __restrict__ wea, const float* __restrict__ bea,
                            const float* __restrict__ web, const float* __restrict__ beb) {
    int idx = blockIdx.x * blockDim.x + threadIdx.x;
    if (idx == 0) { g_unit_ctr = 0; g_cflag = 1; }
    if (idx < 2 * 4 * 64 * 64) {
        int L = idx >> 14;
        int r = idx & 16383;
        int e = r >> 12;
        int d = (r >> 6) & 63;
        int f = r & 63;
        const float* w = L ? web : wea;
        float v = w[(e * 64 + d) * 64 + f];
        int chunk = (e * 8 + (d >> 3)) ^ (f & 7);
        g_wswz[L][f * 256 + chunk * 8 + (d & 7)] = __float2bfloat16(v);
    }
    if (idx < 2 * 4 * 64) {
        int L = idx >> 8;
        int e = (idx >> 6) & 3;
        int f = idx & 63;
        const float* w = L ? web : wea;
        const float* b = L ? beb : bea;
        float s = 0.f;
        for (int d = 0; d < 64; d++)
            s += b[e * 64 + d] * w[(e * 64 + d) * 64 + f];
        g_c[L][f * 4 + e] = s;
        if (s != 0.f) atomicExch(&g_cflag, 0);
    }
}

// ------------------------------- main kernel ------------------------------

__global__ void __launch_bounds__(512, 1)
moe_kernel(const float* __restrict__ x,
           const float* __restrict__ wg_a,
           const float* __restrict__ wg_b,
           float* __restrict__ out,
           int nunits_i) {
    extern __shared__ char smem[];
    const uint32_t sb = smem_u32(smem);
    const int tid  = threadIdx.x;
    const int lane = tid & 31;
    const int warp = tid >> 5;          // 0..15
    const int half = warp & 1;
    const int pair = warp >> 1;         // 0..7
    const int barid = 1 + pair;
    const unsigned nunits = (unsigned)nunits_i;

    // ---- one-time cooperative copies ----
    {
        const uint4* s0 = reinterpret_cast<const uint4*>(g_wswz);
        uint4* dW = reinterpret_cast<uint4*>(smem + SM_W);
        #pragma unroll
        for (int i = tid; i < 4096; i += 512) dW[i] = s0[i];
        float* wga_s = reinterpret_cast<float*>(smem + SM_WGA);
        float* wgb_s = reinterpret_cast<float*>(smem + SM_WGB);
        float* ca_s  = reinterpret_cast<float*>(smem + SM_CA);
        float* cb_s  = reinterpret_cast<float*>(smem + SM_CB);
        if (tid < 256) {
            wga_s[tid] = wg_a[tid]; wgb_s[tid] = wg_b[tid];
            ca_s[tid]  = g_c[0][tid]; cb_s[tid] = g_c[1][tid];
        }
    }
    const bool nofold = (g_cflag != 0);

    const int ql = lane & 3;
    const int qr = lane >> 2;
    const uint32_t ctl = sb + (uint32_t)(SM_CTL + pair * 8);
    const char* stage = smem + SM_STAGE + pair * STAGE_PAIR;
    const uint32_t stage_u = sb + (uint32_t)(SM_STAGE + pair * STAGE_PAIR);
    const char* hbuf = smem + SM_H + pair * H_PAIR;
    const uint32_t hbuf_u = sb + (uint32_t)(SM_H + pair * H_PAIR);
    const float* WGAf = reinterpret_cast<const float*>(smem + SM_WGA);
    const float* WGBf = reinterpret_cast<const float*>(smem + SM_WGB);

    // ---- initial pair steal ----
    if (half == 0 && lane == 0) {
        unsigned v = atomicAdd(&g_unit_ctr, 1u);
        st_ctl(ctl, v);
    }
    __syncthreads();
    unsigned u = ld_ctl(ctl);
    if (u < nunits) issue_stage(x, u, stage_u, half, lane);

    while (u < nunits) {
        // leader steals next unit for the pair
        if (half == 0 && lane == 0) {
            unsigned v = atomicAdd(&g_unit_ctr, 1u);
            st_ctl(ctl, v);
        }
        stage_wait();                 // own cp.async group done
        barpair(barid);               // partner's stage half done + un visible
        const unsigned un = ld_ctl(ctl);
        const size_t rowbase = (size_t)u * 32;

        // ---- X fragments from pair stage (full 32 rows) ----
        uint32_t xf[2][4][4];
        #pragma unroll
        for (int m = 0; m < 2; m++) {
            const char* r0p = stage + (m * 16 + qr) * STAGE_ROW;
            const char* r8p = r0p + 8 * STAGE_ROW;
            #pragma unroll
            for (int kt = 0; kt < 4; kt++) {
                const int cb = (kt * 16 + ql * 2) * 4;
                float2 f0 = *reinterpret_cast<const float2*>(r0p + cb);
                float2 f1 = *reinterpret_cast<const float2*>(r8p + cb);
                float2 f2 = *reinterpret_cast<const float2*>(r0p + cb + 32);
                float2 f3 = *reinterpret_cast<const float2*>(r8p + cb + 32);
                xf[m][kt][0] = pack_bf2(f0.x, f0.y);
                xf[m][kt][1] = pack_bf2(f1.x, f1.y);
                xf[m][kt][2] = pack_bf2(f2.x, f2.y);
                xf[m][kt][3] = pack_bf2(f3.x, f3.y);
            }
        }

        // ---- gates A (duplicated in both warps of the pair) ----
        float4 gAf[2][2];
        uint32_t gA2[4][2][2];
        {
            uint32_t w0[4], w1[4];
            build_wg(WGAf, ql, qr, w0, w1);
            #pragma unroll
            for (int m = 0; m < 2; m++) {
                uint32_t g2c[4][2];
                gates_core(xf[m], w0, w1, ql, g2c, nofold ? nullptr : gAf[m]);
                #pragma unroll
                for (int e = 0; e < 4; e++) { gA2[e][m][0] = g2c[e][0]; gA2[e][m][1] = g2c[e][1]; }
            }
        }

        // ---- layer A (own 32-col half) ----
        float acc[2][4][4];
        if (nofold) {
            #pragma unroll
            for (int n = 0; n < 4; n++)
                #pragma unroll
                for (int m = 0; m < 2; m++) {
                    acc[m][n][0] = 0.f; acc[m][n][1] = 0.f;
                    acc[m][n][2] = 0.f; acc[m][n][3] = 0.f;
                }
        } else {
            const float4* CA4 = reinterpret_cast<const float4*>(smem + SM_CA);
            #pragma unroll
            for (int n = 0; n < 4; n++) {
                int c = half * 32 + n * 8 + ql * 2;
                float4 c0 = CA4[c], c1 = CA4[c + 1];
                #pragma unroll
                for (int m = 0; m < 2; m++) {
                    acc[m][n][0] = -dot4(gAf[m][0], c0);
                    acc[m][n][1] = -dot4(gAf[m][0], c1);
                    acc[m][n][2] = -dot4(gAf[m][1], c0);
                    acc[m][n][3] = -dot4(gAf[m][1], c1);
                }
            }
        }
        run_layer_half(acc, xf, gA2, sb + SM_W + (uint32_t)half * 16384u, lane);

        // ---- write own bf16 h half to pair h-buffer ----
        #pragma unroll
        for (int m = 0; m < 2; m++) {
            #pragma unroll
            for (int n = 0; n < 4; n++) {
                int c = half * 32 + n * 8 + ql * 2;
                int rl = m * 16 + qr;
                *reinterpret_cast<uint32_t*>(const_cast<char*>(hbuf) + rl * H_ROW + c * 2)
                    = pack_bf2(acc[m][n][0], acc[m][n][1]);
                *reinterpret_cast<uint32_t*>(const_cast<char*>(hbuf) + (rl + 8) * H_ROW + c * 2)
                    = pack_bf2(acc[m][n][2], acc[m][n][3]);
            }
        }
        barpair(barid);               // full h available

        // ---- load full h fragments (bf16 pairs, direct) ----
        #pragma unroll
        for (int m = 0; m < 2; m++) {
            const char* h0 = hbuf + (m * 16 + qr) * H_ROW;
            const char* h8 = h0 + 8 * H_ROW;
            #pragma unroll
            for (int kt = 0; kt < 4; kt++) {
                const int cb = (kt * 16 + ql * 2) * 2;
                xf[m][kt][0] = *reinterpret_cast<const uint32_t*>(h0 + cb);
                xf[m][kt][1] = *reinterpret_cast<const uint32_t*>(h8 + cb);
                xf[m][kt][2] = *reinterpret_cast<const uint32_t*>(h0 + cb + 16);
                xf[m][kt][3] = *reinterpret_cast<const uint32_t*>(h8 + cb + 16);
            }
        }

        // ---- gates B ----
        float4 gBf[2][2];
        uint32_t gB2[4][2][2];
        {
            uint32_t w0[4], w1[4];
            build_wg(WGBf, ql, qr, w0, w1);
            #pragma unroll
            for (int m = 0; m < 2; m++) {
                uint32_t g2c[4][2];
                gates_core(xf[m], w0, w1, ql, g2c, nofold ? nullptr : gBf[m]);
                #pragma unroll
                for (int e = 0; e < 4; e++) { gB2[e][m][0] = g2c[e][0]; gB2[e][m][1] = g2c[e][1]; }
            }
        }

        // ---- layer B acc init: residual (own cols, from stage) [- fold] ----
        if (nofold) {
            #pragma unroll
            for (int n = 0; n < 4; n++) {
                int c = half * 32 + n * 8 + ql * 2;
                #pragma unroll
                for (int m = 0; m < 2; m++) {
                    const char* rlp = stage + (m * 16 + qr) * STAGE_ROW + c * 4;
                    float2 xl = *reinterpret_cast<const float2*>(rlp);
                    float2 xh = *reinterpret_cast<const float2*>(rlp + 8 * STAGE_ROW);
                    acc[m][n][0] = xl.x; acc[m][n][1] = xl.y;
                    acc[m][n][2] = xh.x; acc[m][n][3] = xh.y;
                }
            }
        } else {
            const float4* CB4 = reinterpret_cast<const float4*>(smem + SM_CB);
            #pragma unroll
            for (int n = 0; n < 4; n++) {
                int c = half * 32 + n * 8 + ql * 2;
                float4 c0 = CB4[c], c1 = CB4[c + 1];
                #pragma unroll
                for (int m = 0; m < 2; m++) {
                    const char* rlp = stage + (m * 16 + qr) * STAGE_ROW + c * 4;
                    float2 xl = *reinterpret_cast<const float2*>(rlp);
                    float2 xh = *reinterpret_cast<const float2*>(rlp + 8 * STAGE_ROW);
                    acc[m][n][0] = xl.x - dot4(gBf[m][0], c0);
                    acc[m][n][1] = xl.y - dot4(gBf[m][0], c1);
                    acc[m][n][2] = xh.x - dot4(gBf[m][1], c0);
                    acc[m][n][3] = xh.y - dot4(gBf[m][1], c1);
                }
            }
        }
        barpair(barid);               // both warps done reading stage
        if (un < nunits) issue_stage(x, un, stage_u, half, lane);

        run_layer_half(acc, xf, gB2, sb + SM_W + 32768u + (uint32_t)half * 16384u, lane);

        // ---- epilogue: own cols, streaming stores ----
        #pragma unroll
        for (int m = 0; m < 2; m++) {
            const size_t rl = rowbase + (size_t)(m * 16 + qr);
            const size_t rh = rl + 8;
            #pragma unroll
            for (int n = 0; n < 4; n++) {
                int c = half * 32 + n * 8 + ql * 2;
                __stcs(reinterpret_cast<float2*>(out + rl * 64 + c),
                       make_float2(acc[m][n][0], acc[m][n][1]));
                __stcs(reinterpret_cast<float2*>(out + rh * 64 + c),
                       make_float2(acc[m][n][2], acc[m][n][3]));
            }
        }

        u = un;
    }
}

// ------------------------------- launch -----------------------------------

extern "C" void kernel_launch(void* const* d_in, const int* in_sizes, int n_in,
                              void* d_out, int out_size) {
    const float* x   = (const float*)d_in[0];
    const float* wga = (const float*)d_in[1];
    const float* wea = (const float*)d_in[2];
    const float* bea = (const float*)d_in[3];
    const float* wgb = (const float*)d_in[4];
    const float* web = (const float*)d_in[5];
    const float* beb = (const float*)d_in[6];
    float* out = (float*)d_out;

    const int ntok   = in_sizes[0] / 64;
    const int nunits = ntok / 32;

    prep_kernel<<<64, 512>>>(wea, bea, web, beb);

    cudaFuncSetAttribute(moe_kernel, cudaFuncAttributeMaxDynamicSharedMemorySize, SMEM_TOTAL);
    moe_kernel<<<GRID, 512, SMEM_TOTAL>>>(x, wga, wgb, out, nunits);
}

// round 16
// speedup vs baseline: 1.1163x; 1.1163x over previous
#include <cuda_runtime.h>
#include <cuda_bf16.h>
#include <cstdint>

// ---------------------------------------------------------------------------
// SPMoEAdaptor: out = moe_b(moe_a(x)) + x
//   moe(x) = sum_e softmax(x@Wg)[:,e] * ((x - b_e) @ W_e)
// R15: M-split persistent warps. Unit = 16 rows (one m16n8k16 A-tile) per
// warp, full N=64: acc is 32 regs, xf 16 regs -> 512-thread CTA fits <=128
// regs without spills and with ZERO duplicated work (unlike R14's N-split:
// no pairing, no barriers, no h exchange — layer B needs only own rows' h).
// 16 warps/SM (4/SMSP) with unchanged per-warp MMA density. Rest as champion:
// bf16 HMMA, cp.async x-stage, work-stealing, zero-bias fast path, streaming
// stores. LDSM/MMA ratio doubles (L1 ~75-80% predicted, below cap).
// ---------------------------------------------------------------------------

namespace {
constexpr int SM_W     = 0;             // 64KB bf16 weights, both layers (n-major)
constexpr int SM_WGA   = 65536;         // 64 x float4 (w_gate_a as [d][e])
constexpr int SM_WGB   = 66560;
constexpr int SM_CA    = 67584;         // 64 x float4 (c_a as [f][e])
constexpr int SM_CB    = 68608;
constexpr int SM_STAGE = 69632;         // 16 warps x 16 rows x 288B x-stage
constexpr int STAGE_ROW  = 288;         // 256B data + 32B pad (bank-conflict-free)
constexpr int STAGE_WARP = 16 * STAGE_ROW;   // 4608
constexpr int SMEM_TOTAL = SM_STAGE + 16 * STAGE_WARP;  // 143360

constexpr int GRID = 148;               // 1 CTA per SM, 512 threads
}

// device-global scratch (allocation-free rule)
__device__ __align__(16) __nv_bfloat16 g_wswz[2][64 * 256];
__device__ __align__(16) float g_c[2][64 * 4];   // c[L][f*4+e] = (b_e @ W_e)[f]
__device__ unsigned g_unit_ctr;                  // work-stealing counter
__device__ int g_cflag;                          // 1 iff all c == 0 (fast path)

// ------------------------------- helpers ----------------------------------

__device__ __forceinline__ uint32_t smem_u32(const void* p) {
    uint32_t a;
    asm("{ .reg .u64 t; cvta.to.shared.u64 t, %1; cvt.u32.u64 %0, t; }" : "=r"(a) : "l"(p));
    return a;
}

__device__ __forceinline__ void ldsm_x4(uint32_t* r, uint32_t addr) {
    asm volatile("ldmatrix.sync.aligned.m8n8.x4.shared.b16 {%0,%1,%2,%3}, [%4];"
                 : "=r"(r[0]), "=r"(r[1]), "=r"(r[2]), "=r"(r[3]) : "r"(addr));
}

__device__ __forceinline__ void mma_bf16(float* d, const uint32_t* a,
                                         uint32_t b0, uint32_t b1) {
    asm volatile("mma.sync.aligned.m16n8k16.row.col.f32.bf16.bf16.f32 "
                 "{%0,%1,%2,%3}, {%4,%5,%6,%7}, {%8,%9}, {%0,%1,%2,%3};"
                 : "+f"(d[0]), "+f"(d[1]), "+f"(d[2]), "+f"(d[3])
                 : "r"(a[0]), "r"(a[1]), "r"(a[2]), "r"(a[3]), "r"(b0), "r"(b1));
}

__device__ __forceinline__ uint32_t pack_bf2(float lo, float hi) {
    __nv_bfloat162 t = __floats2bfloat162_rn(lo, hi);
    return *reinterpret_cast<uint32_t*>(&t);
}

__device__ __forceinline__ uint32_t bf2bcast(float v) { return pack_bf2(v, v); }

__device__ __forceinline__ uint32_t hmul2u(uint32_t a, uint32_t b) {
    __nv_bfloat162 r = __hmul2(*reinterpret_cast<__nv_bfloat162*>(&a),
                               *reinterpret_cast<__nv_bfloat162*>(&b));
    return *reinterpret_cast<uint32_t*>(&r);
}

__device__ __forceinline__ float dot4(float4 a, float4 b) {
    return a.x * b.x + a.y * b.y + a.z * b.z + a.w * b.w;
}

__device__ __forceinline__ float4 softmax4(float4 l) {
    float mx = fmaxf(fmaxf(l.x, l.y), fmaxf(l.z, l.w));
    float e0 = __expf(l.x - mx), e1 = __expf(l.y - mx),
          e2 = __expf(l.z - mx), e3 = __expf(l.w - mx);
    float inv = 1.f / (e0 + e1 + e2 + e3);
    return make_float4(e0 * inv, e1 * inv, e2 * inv, e3 * inv);
}

__device__ __forceinline__ unsigned steal(int lane) {
    unsigned v = 0;
    if (lane == 0) v = atomicAdd(&g_unit_ctr, 1u);
    return __shfl_sync(0xffffffffu, v, 0);
}

// copy unit u's 16x64 fp32 x-rows into this warp's stage (8 chunks/lane)
__device__ __forceinline__ void issue_stage(const float* __restrict__ x, unsigned u,
                                            uint32_t dstbase, int lane) {
    const float* src = x + (size_t)u * 16 * 64;
    const int hl = lane >> 4;      // 0/1
    const int ch = lane & 15;      // 16B chunk within row
    #pragma unroll
    for (int i = 0; i < 8; i++) {
        int row = 2 * i + hl;
        uint32_t dst = dstbase + (uint32_t)(row * STAGE_ROW + ch * 16);
        const float* s = src + row * 64 + ch * 4;
        asm volatile("cp.async.cg.shared.global [%0], [%1], 16;" :: "r"(dst), "l"(s));
    }
    asm volatile("cp.async.commit_group;" ::: "memory");
}

__device__ __forceinline__ void stage_wait() {
    asm volatile("cp.async.wait_group 0;" ::: "memory");
    __syncwarp();
}

// one MoE GEMM layer, M=16: per (e,kt) batch all 4 ldsm.x4 (MLP=4), then 4
// hmul2 scalings (fills LDS wait), then 8 MMAs.
__device__ __forceinline__ void run_layer(float acc[8][4],
                                          const uint32_t xf[4][4],
                                          const uint32_t g2[4][2],
                                          uint32_t wbase, int lane) {
    const int l7 = lane & 7;
    const uint32_t lane_row = (uint32_t)(((lane >> 4) & 1) * 8 + l7);
    const uint32_t kh = (uint32_t)((lane >> 3) & 1);
    const uint32_t lane_base = wbase + lane_row * 512u;
    #pragma unroll
    for (int e = 0; e < 4; e++) {
        #pragma unroll
        for (int kt = 0; kt < 4; kt++) {
            const uint32_t c0 = (uint32_t)(e * 8 + kt * 2) + kh;
            const uint32_t coff = ((c0 ^ (uint32_t)l7) << 4);
            uint32_t bb[4][4];
            #pragma unroll
            for (int np = 0; np < 4; np++)
                ldsm_x4(bb[np], lane_base + (uint32_t)np * 8192u + coff);
            uint32_t a[4];
            a[0] = hmul2u(xf[kt][0], g2[e][0]);
            a[1] = hmul2u(xf[kt][1], g2[e][1]);
            a[2] = hmul2u(xf[kt][2], g2[e][0]);
            a[3] = hmul2u(xf[kt][3], g2[e][1]);
            #pragma unroll
            for (int np = 0; np < 4; np++) {
                mma_bf16(acc[2 * np],     a, bb[np][0], bb[np][1]);
                mma_bf16(acc[2 * np + 1], a, bb[np][2], bb[np][3]);
            }
        }
    }
}

// gates for one 16-row tile: tensor-core logits -> softmax -> bcast pairs.
// gf written only when wanted (general path bias folds).
__device__ __forceinline__ void gates_core(const uint32_t xf[4][4],
                                           const uint32_t* wg0,
                                           const uint32_t* wg1,
                                           int ql, uint32_t g2[4][2],
                                           float4* gf) {
    float l[4]  = {0.f, 0.f, 0.f, 0.f};
    float l2[4] = {0.f, 0.f, 0.f, 0.f};
    mma_bf16(l,  xf[0], wg0[0], wg1[0]);
    mma_bf16(l2, xf[1], wg0[1], wg1[1]);
    mma_bf16(l,  xf[2], wg0[2], wg1[2]);
    mma_bf16(l2, xf[3], wg0[3], wg1[3]);
    l[0] += l2[0]; l[1] += l2[1]; l[2] += l2[2]; l[3] += l2[3];
    float r0 = __shfl_xor_sync(0xffffffffu, l[0], 1);
    float r1 = __shfl_xor_sync(0xffffffffu, l[1], 1);
    float r2 = __shfl_xor_sync(0xffffffffu, l[2], 1);
    float r3 = __shfl_xor_sync(0xffffffffu, l[3], 1);
    bool even = (ql & 1) == 0;
    float4 La = even ? make_float4(l[0], l[1], r0, r1)
                     : make_float4(r0, r1, l[0], l[1]);
    float4 Lb = even ? make_float4(l[2], l[3], r2, r3)
                     : make_float4(r2, r3, l[2], l[3]);
    float4 ga = softmax4(La);
    float4 gb = softmax4(Lb);
    if (gf) { gf[0] = ga; gf[1] = gb; }
    g2[0][0] = bf2bcast(ga.x); g2[1][0] = bf2bcast(ga.y);
    g2[2][0] = bf2bcast(ga.z); g2[3][0] = bf2bcast(ga.w);
    g2[0][1] = bf2bcast(gb.x); g2[1][1] = bf2bcast(gb.y);
    g2[2][1] = bf2bcast(gb.z); g2[3][1] = bf2bcast(gb.w);
}

// ------------------------------- prep kernel ------------------------------

__global__ void prep_kernel(const float* __restrict__ wea, const float* __restrict__ bea,
                            const float* __restrict__ web, const float* __restrict__ beb) {
    int idx = blockIdx.x * blockDim.x + threadIdx.x;
    if (idx == 0) { g_unit_ctr = 0; g_cflag = 1; }
    if (idx < 2 * 4 * 64 * 64) {
        int L = idx >> 14;
        int r = idx & 16383;
        int e = r >> 12;
        int d = (r >> 6) & 63;
        int f = r & 63;
        const float* w = L ? web : wea;
        float v = w[(e * 64 + d) * 64 + f];
        int chunk = (e * 8 + (d >> 3)) ^ (f & 7);
        g_wswz[L][f * 256 + chunk * 8 + (d & 7)] = __float2bfloat16(v);
    }
    if (idx < 2 * 4 * 64) {
        int L = idx >> 8;
        int e = (idx >> 6) & 3;
        int f = idx & 63;
        const float* w = L ? web : wea;
        const float* b = L ? beb : bea;
        float s = 0.f;
        for (int d = 0; d < 64; d++)
            s += b[e * 64 + d] * w[(e * 64 + d) * 64 + f];
        g_c[L][f * 4 + e] = s;
        if (s != 0.f) atomicExch(&g_cflag, 0);
    }
}

// ------------------------------- main kernel ------------------------------

__global__ void __launch_bounds__(512, 1)
moe_kernel(const float* __restrict__ x,
           const float* __restrict__ wg_a,
           const float* __restrict__ wg_b,
           float* __restrict__ out,
           int nunits_i) {
    extern __shared__ char smem[];
    const uint32_t sb = smem_u32(smem);
    const int tid  = threadIdx.x;
    const int lane = tid & 31;
    const int warp = tid >> 5;          // 0..15
    const unsigned nunits = (unsigned)nunits_i;

    // ---- one-time cooperative copies ----
    {
        const uint4* s0 = reinterpret_cast<const uint4*>(g_wswz);
        uint4* dW = reinterpret_cast<uint4*>(smem + SM_W);
        #pragma unroll
        for (int i = tid; i < 4096; i += 512) dW[i] = s0[i];
        float* wga_s = reinterpret_cast<float*>(smem + SM_WGA);
        float* wgb_s = reinterpret_cast<float*>(smem + SM_WGB);
        float* ca_s  = reinterpret_cast<float*>(smem + SM_CA);
        float* cb_s  = reinterpret_cast<float*>(smem + SM_CB);
        if (tid < 256) {
            wga_s[tid] = wg_a[tid]; wgb_s[tid] = wg_b[tid];
            ca_s[tid]  = g_c[0][tid]; cb_s[tid] = g_c[1][tid];
        }
    }
    const bool nofold = (g_cflag != 0);
    __syncthreads();

    const int ql = lane & 3;
    const int qr = lane >> 2;
    const char* stage = smem + SM_STAGE + warp * STAGE_WARP;
    const uint32_t stage_u32 = sb + (uint32_t)(SM_STAGE + warp * STAGE_WARP);

    // ---- Wg B-fragments (tile-invariant) ----
    uint32_t wgA0[4], wgA1[4], wgB0[4], wgB1[4];
    {
        const float* WGAf = reinterpret_cast<const float*>(smem + SM_WGA);
        const float* WGBf = reinterpret_cast<const float*>(smem + SM_WGB);
        const int e4 = qr & 3;
        #pragma unroll
        for (int kt = 0; kt < 4; kt++) {
            int d0 = kt * 16 + 2 * ql;
            wgA0[kt] = pack_bf2(WGAf[d0 * 4 + e4],       WGAf[(d0 + 1) * 4 + e4]);
            wgA1[kt] = pack_bf2(WGAf[(d0 + 8) * 4 + e4], WGAf[(d0 + 9) * 4 + e4]);
            wgB0[kt] = pack_bf2(WGBf[d0 * 4 + e4],       WGBf[(d0 + 1) * 4 + e4]);
            wgB1[kt] = pack_bf2(WGBf[(d0 + 8) * 4 + e4], WGBf[(d0 + 9) * 4 + e4]);
        }
    }

    unsigned u = steal(lane);
    if (u < nunits) issue_stage(x, u, stage_u32, lane);

    while (u < nunits) {
        unsigned un = steal(lane);      // pipelined next-unit fetch
        const size_t rowbase = (size_t)u * 16;

        stage_wait();                   // x for unit u ready in smem

        // ---- X fragments from stage (rows qr, qr+8) ----
        uint32_t xf[4][4];
        {
            const char* r0p = stage + qr * STAGE_ROW;
            const char* r8p = r0p + 8 * STAGE_ROW;
            #pragma unroll
            for (int kt = 0; kt < 4; kt++) {
                const int cb = (kt * 16 + ql * 2) * 4;
                float2 f0 = *reinterpret_cast<const float2*>(r0p + cb);
                float2 f1 = *reinterpret_cast<const float2*>(r8p + cb);
                float2 f2 = *reinterpret_cast<const float2*>(r0p + cb + 32);
                float2 f3 = *reinterpret_cast<const float2*>(r8p + cb + 32);
                xf[kt][0] = pack_bf2(f0.x, f0.y);
                xf[kt][1] = pack_bf2(f1.x, f1.y);
                xf[kt][2] = pack_bf2(f2.x, f2.y);
                xf[kt][3] = pack_bf2(f3.x, f3.y);
            }
        }

        // ---- gates A ----
        float4 gAf[2];
        uint32_t gA2[4][2];
        gates_core(xf, wgA0, wgA1, ql, gA2, nofold ? nullptr : gAf);

        // ---- layer A: acc init (zero or bias fold), GEMM ----
        float acc[8][4];
        if (nofold) {
            #pragma unroll
            for (int n = 0; n < 8; n++) {
                acc[n][0] = 0.f; acc[n][1] = 0.f; acc[n][2] = 0.f; acc[n][3] = 0.f;
            }
        } else {
            const float4* CA4 = reinterpret_cast<const float4*>(smem + SM_CA);
            #pragma unroll
            for (int n = 0; n < 8; n++) {
                int c = n * 8 + ql * 2;
                float4 c0 = CA4[c], c1 = CA4[c + 1];
                acc[n][0] = -dot4(gAf[0], c0);
                acc[n][1] = -dot4(gAf[0], c1);
                acc[n][2] = -dot4(gAf[1], c0);
                acc[n][3] = -dot4(gAf[1], c1);
            }
        }
        run_layer(acc, xf, gA2, sb + SM_W, lane);

        // ---- repack h: C-frag layout == A-frag layout (per kt) ----
        #pragma unroll
        for (int kt = 0; kt < 4; kt++) {
            xf[kt][0] = pack_bf2(acc[2*kt][0],   acc[2*kt][1]);
            xf[kt][1] = pack_bf2(acc[2*kt][2],   acc[2*kt][3]);
            xf[kt][2] = pack_bf2(acc[2*kt+1][0], acc[2*kt+1][1]);
            xf[kt][3] = pack_bf2(acc[2*kt+1][2], acc[2*kt+1][3]);
        }

        // ---- gates B ----
        float4 gBf[2];
        uint32_t gB2[4][2];
        gates_core(xf, wgB0, wgB1, ql, gB2, nofold ? nullptr : gBf);

        // ---- layer B acc init: residual (from stage) [- bias fold] ----
        if (nofold) {
            #pragma unroll
            for (int n = 0; n < 8; n++) {
                int c = n * 8 + ql * 2;
                const char* rlp = stage + qr * STAGE_ROW + c * 4;
                float2 xl = *reinterpret_cast<const float2*>(rlp);
                float2 xh = *reinterpret_cast<const float2*>(rlp + 8 * STAGE_ROW);
                acc[n][0] = xl.x; acc[n][1] = xl.y;
                acc[n][2] = xh.x; acc[n][3] = xh.y;
            }
        } else {
            const float4* CB4 = reinterpret_cast<const float4*>(smem + SM_CB);
            #pragma unroll
            for (int n = 0; n < 8; n++) {
                int c = n * 8 + ql * 2;
                float4 c0 = CB4[c], c1 = CB4[c + 1];
                const char* rlp = stage + qr * STAGE_ROW + c * 4;
                float2 xl = *reinterpret_cast<const float2*>(rlp);
                float2 xh = *reinterpret_cast<const float2*>(rlp + 8 * STAGE_ROW);
                acc[n][0] = xl.x - dot4(gBf[0], c0);
                acc[n][1] = xl.y - dot4(gBf[0], c1);
                acc[n][2] = xh.x - dot4(gBf[1], c0);
                acc[n][3] = xh.y - dot4(gBf[1], c1);
            }
        }

        // ---- stage free: kick off next unit's cp.async, then layer B GEMM --
        __syncwarp();
        if (un < nunits) issue_stage(x, un, stage_u32, lane);

        run_layer(acc, xf, gB2, sb + SM_W + 32768u, lane);

        // ---- epilogue: streaming stores (rows rowbase+qr, +8) ----
        {
            const size_t rl = rowbase + (size_t)qr;
            const size_t rh = rl + 8;
            #pragma unroll
            for (int n = 0; n < 8; n++) {
                int c = n * 8 + ql * 2;
                __stcs(reinterpret_cast<float2*>(out + rl * 64 + c),
                       make_float2(acc[n][0], acc[n][1]));
                __stcs(reinterpret_cast<float2*>(out + rh * 64 + c),
                       make_float2(acc[n][2], acc[n][3]));
            }
        }

        u = un;
    }
}

// ------------------------------- launch -----------------------------------

extern "C" void kernel_launch(void* const* d_in, const int* in_sizes, int n_in,
                              void* d_out, int out_size) {
    const float* x   = (const float*)d_in[0];
    const float* wga = (const float*)d_in[1];
    const float* wea = (const float*)d_in[2];
    const float* bea = (const float*)d_in[3];
    const float* wgb = (const float*)d_in[4];
    const float* web = (const float*)d_in[5];
    const float* beb = (const float*)d_in[6];
    float* out = (float*)d_out;

    const int ntok   = in_sizes[0] / 64;
    const int nunits = ntok / 16;

    prep_kernel<<<64, 512>>>(wea, bea, web, beb);

    cudaFuncSetAttribute(moe_kernel, cudaFuncAttributeMaxDynamicSharedMemorySize, SMEM_TOTAL);
    moe_kernel<<<GRID, 512, SMEM_TOTAL>>>(x, wga, wgb, out, nunits);
}

// round 17
// speedup vs baseline: 1.1796x; 1.0567x over previous
#include <cuda_runtime.h>
#include <cuda_fp16.h>
#include <cstdint>

// ---------------------------------------------------------------------------
// SPMoEAdaptor: out = moe_b(moe_a(x)) + x
//   moe(x) = sum_e softmax(x@Wg)[:,e] * ((x - b_e) @ W_e)
// R16: fp16 expert GEMMs (mma.m16n8k16 f16 D/C): accumulators are packed
// f16x2 -> 32 regs at M=32, so 16 warps/SM (512 thr, <=128 regs) with the
// BALANCED M=32 LDSM ratio (R15 showed M=16 is L1-capped at 85%). The f16
// D-fragment layout equals the A-fragment layout -> layer-B repack is pure
// register renaming. Residual added in fp32 at the epilogue (never swamped
// into the f16 acc); gates keep f32 accumulation. cp.async x-stage,
// work-stealing, zero-bias fast path, streaming stores as champion.
// ---------------------------------------------------------------------------

namespace {
constexpr int SM_W     = 0;             // 64KB f16 weights, both layers (n-major)
constexpr int SM_WGA   = 65536;         // 64 x float4 (w_gate_a as [d][e])
constexpr int SM_WGB   = 66560;
constexpr int SM_CA    = 67584;         // 64 x float4 (c_a as [f][e])
constexpr int SM_CB    = 68608;
constexpr int SM_STAGE = 69632;         // 16 warps x 32 rows x 288B x-stage
constexpr int STAGE_ROW  = 288;         // 256B data + 32B pad (bank-conflict-free)
constexpr int STAGE_WARP = 32 * STAGE_ROW;   // 9216
constexpr int SMEM_TOTAL = SM_STAGE + 16 * STAGE_WARP;  // 217088

constexpr int GRID = 148;               // 1 CTA per SM, 512 threads
}

// device-global scratch (allocation-free rule)
// n-major: row f (0..63), 256 f16 per row (k = e*64+d), chunk-XOR swizzled.
__device__ __align__(16) __half g_wswz[2][64 * 256];
__device__ __align__(16) float g_c[2][64 * 4];   // c[L][f*4+e] = (b_e @ W_e)[f]
__device__ unsigned g_unit_ctr;                  // work-stealing counter
__device__ int g_cflag;                          // 1 iff all c == 0 (fast path)

// ------------------------------- helpers ----------------------------------

__device__ __forceinline__ uint32_t smem_u32(const void* p) {
    uint32_t a;
    asm("{ .reg .u64 t; cvta.to.shared.u64 t, %1; cvt.u32.u64 %0, t; }" : "=r"(a) : "l"(p));
    return a;
}

__device__ __forceinline__ void ldsm_x4(uint32_t* r, uint32_t addr) {
    asm volatile("ldmatrix.sync.aligned.m8n8.x4.shared.b16 {%0,%1,%2,%3}, [%4];"
                 : "=r"(r[0]), "=r"(r[1]), "=r"(r[2]), "=r"(r[3]) : "r"(addr));
}

// f16 x f16 -> f16 accumulate (packed f16x2 D/C, 2 regs)
__device__ __forceinline__ void mma_f16(uint32_t* d, const uint32_t* a,
                                        uint32_t b0, uint32_t b1) {
    asm volatile("mma.sync.aligned.m16n8k16.row.col.f16.f16.f16.f16 "
                 "{%0,%1}, {%2,%3,%4,%5}, {%6,%7}, {%0,%1};"
                 : "+r"(d[0]), "+r"(d[1])
                 : "r"(a[0]), "r"(a[1]), "r"(a[2]), "r"(a[3]), "r"(b0), "r"(b1));
}

// f16 x f16 -> f32 accumulate (for gates)
__device__ __forceinline__ void mma_f16_f32(float* d, const uint32_t* a,
                                            uint32_t b0, uint32_t b1) {
    asm volatile("mma.sync.aligned.m16n8k16.row.col.f32.f16.f16.f32 "
                 "{%0,%1,%2,%3}, {%4,%5,%6,%7}, {%8,%9}, {%0,%1,%2,%3};"
                 : "+f"(d[0]), "+f"(d[1]), "+f"(d[2]), "+f"(d[3])
                 : "r"(a[0]), "r"(a[1]), "r"(a[2]), "r"(a[3]), "r"(b0), "r"(b1));
}

__device__ __forceinline__ uint32_t pack_h2(float lo, float hi) {
    __half2 t = __floats2half2_rn(lo, hi);
    return *reinterpret_cast<uint32_t*>(&t);
}

__device__ __forceinline__ uint32_t h2bcast(float v) { return pack_h2(v, v); }

__device__ __forceinline__ float2 unpack_h2(uint32_t v) {
    return __half22float2(*reinterpret_cast<__half2*>(&v));
}

__device__ __forceinline__ uint32_t hmul2u(uint32_t a, uint32_t b) {
    __half2 r = __hmul2(*reinterpret_cast<__half2*>(&a),
                        *reinterpret_cast<__half2*>(&b));
    return *reinterpret_cast<uint32_t*>(&r);
}

__device__ __forceinline__ float dot4(float4 a, float4 b) {
    return a.x * b.x + a.y * b.y + a.z * b.z + a.w * b.w;
}

__device__ __forceinline__ float4 softmax4(float4 l) {
    float mx = fmaxf(fmaxf(l.x, l.y), fmaxf(l.z, l.w));
    float e0 = __expf(l.x - mx), e1 = __expf(l.y - mx),
          e2 = __expf(l.z - mx), e3 = __expf(l.w - mx);
    float inv = 1.f / (e0 + e1 + e2 + e3);
    return make_float4(e0 * inv, e1 * inv, e2 * inv, e3 * inv);
}

__device__ __forceinline__ unsigned steal(int lane) {
    unsigned v = 0;
    if (lane == 0) v = atomicAdd(&g_unit_ctr, 1u);
    return __shfl_sync(0xffffffffu, v, 0);
}

// copy unit u's 32x64 fp32 x-rows into this warp's stage
__device__ __forceinline__ void issue_stage(const float* __restrict__ x, unsigned u,
                                            uint32_t dstbase, int lane) {
    const float* src = x + (size_t)u * 32 * 64;
    const int hl = lane >> 4;
    const int ch = lane & 15;
    #pragma unroll
    for (int i = 0; i < 16; i++) {
        int row = 2 * i + hl;
        uint32_t dst = dstbase + (uint32_t)(row * STAGE_ROW + ch * 16);
        const float* s = src + row * 64 + ch * 4;
        asm volatile("cp.async.cg.shared.global [%0], [%1], 16;" :: "r"(dst), "l"(s));
    }
    asm volatile("cp.async.commit_group;" ::: "memory");
}

__device__ __forceinline__ void stage_wait() {
    asm volatile("cp.async.wait_group 0;" ::: "memory");
    __syncwarp();
}

// one MoE GEMM layer, M=32, f16 acc: per (e,kt) batch 4 ldsm.x4 (MLP=4),
// hmul2 gate-scaling fills the LDS wait, then 16 f16 MMAs.
__device__ __forceinline__ void run_layer(uint32_t acc[2][8][2],
                                          const uint32_t xf[2][4][4],
                                          const uint32_t g2[4][2][2],
                                          uint32_t wbase, int lane) {
    const int l7 = lane & 7;
    const uint32_t lane_row = (uint32_t)(((lane >> 4) & 1) * 8 + l7);
    const uint32_t kh = (uint32_t)((lane >> 3) & 1);
    const uint32_t lane_base = wbase + lane_row * 512u;
    #pragma unroll
    for (int e = 0; e < 4; e++) {
        #pragma unroll
        for (int kt = 0; kt < 4; kt++) {
            const uint32_t c0 = (uint32_t)(e * 8 + kt * 2) + kh;
            const uint32_t coff = ((c0 ^ (uint32_t)l7) << 4);
            uint32_t bb[4][4];
            #pragma unroll
            for (int np = 0; np < 4; np++)
                ldsm_x4(bb[np], lane_base + (uint32_t)np * 8192u + coff);
            uint32_t a[2][4];
            #pragma unroll
            for (int m = 0; m < 2; m++) {
                a[m][0] = hmul2u(xf[m][kt][0], g2[e][m][0]);
                a[m][1] = hmul2u(xf[m][kt][1], g2[e][m][1]);
                a[m][2] = hmul2u(xf[m][kt][2], g2[e][m][0]);
                a[m][3] = hmul2u(xf[m][kt][3], g2[e][m][1]);
            }
            #pragma unroll
            for (int np = 0; np < 4; np++) {
                mma_f16(acc[0][2 * np],     a[0], bb[np][0], bb[np][1]);
                mma_f16(acc[0][2 * np + 1], a[0], bb[np][2], bb[np][3]);
                mma_f16(acc[1][2 * np],     a[1], bb[np][0], bb[np][1]);
                mma_f16(acc[1][2 * np + 1], a[1], bb[np][2], bb[np][3]);
            }
        }
    }
}

// gates: f32-accum tensor-core logits -> softmax -> f16 bcast pairs.
// gf written only on the general path (bias folds).
__device__ __forceinline__ void gates_core(const uint32_t xf[4][4],
                                           const uint32_t* wg0,
                                           const uint32_t* wg1,
                                           int ql, uint32_t g2[4][2],
                                           float4* gf) {
    float l[4]  = {0.f, 0.f, 0.f, 0.f};
    float l2[4] = {0.f, 0.f, 0.f, 0.f};
    mma_f16_f32(l,  xf[0], wg0[0], wg1[0]);
    mma_f16_f32(l2, xf[1], wg0[1], wg1[1]);
    mma_f16_f32(l,  xf[2], wg0[2], wg1[2]);
    mma_f16_f32(l2, xf[3], wg0[3], wg1[3]);
    l[0] += l2[0]; l[1] += l2[1]; l[2] += l2[2]; l[3] += l2[3];
    float r0 = __shfl_xor_sync(0xffffffffu, l[0], 1);
    float r1 = __shfl_xor_sync(0xffffffffu, l[1], 1);
    float r2 = __shfl_xor_sync(0xffffffffu, l[2], 1);
    float r3 = __shfl_xor_sync(0xffffffffu, l[3], 1);
    bool even = (ql & 1) == 0;
    float4 La = even ? make_float4(l[0], l[1], r0, r1)
                     : make_float4(r0, r1, l[0], l[1]);
    float4 Lb = even ? make_float4(l[2], l[3], r2, r3)
                     : make_float4(r2, r3, l[2], l[3]);
    float4 ga = softmax4(La);
    float4 gb = softmax4(Lb);
    if (gf) { gf[0] = ga; gf[1] = gb; }
    g2[0][0] = h2bcast(ga.x); g2[1][0] = h2bcast(ga.y);
    g2[2][0] = h2bcast(ga.z); g2[3][0] = h2bcast(ga.w);
    g2[0][1] = h2bcast(gb.x); g2[1][1] = h2bcast(gb.y);
    g2[2][1] = h2bcast(gb.z); g2[3][1] = h2bcast(gb.w);
}

// ------------------------------- prep kernel ------------------------------

__global__ void prep_kernel(const float* __restrict__ wea, const float* __restrict__ bea,
                            const float* __restrict__ web, const float* __restrict__ beb) {
    int idx = blockIdx.x * blockDim.x + threadIdx.x;
    if (idx == 0) { g_unit_ctr = 0; g_cflag = 1; }
    if (idx < 2 * 4 * 64 * 64) {
        int L = idx >> 14;
        int r = idx & 16383;
        int e = r >> 12;
        int d = (r >> 6) & 63;
        int f = r & 63;
        const float* w = L ? web : wea;
        float v = w[(e * 64 + d) * 64 + f];
        int chunk = (e * 8 + (d >> 3)) ^ (f & 7);
        g_wswz[L][f * 256 + chunk * 8 + (d & 7)] = __float2half(v);
    }
    if (idx < 2 * 4 * 64) {
        int L = idx >> 8;
        int e = (idx >> 6) & 3;
        int f = idx & 63;
        const float* w = L ? web : wea;
        const float* b = L ? beb : bea;
        float s = 0.f;
        for (int d = 0; d < 64; d++)
            s += b[e * 64 + d] * w[(e * 64 + d) * 64 + f];
        g_c[L][f * 4 + e] = s;
        if (s != 0.f) atomicExch(&g_cflag, 0);
    }
}

// ------------------------------- main kernel ------------------------------

__global__ void __launch_bounds__(512, 1)
moe_kernel(const float* __restrict__ x,
           const float* __restrict__ wg_a,
           const float* __restrict__ wg_b,
           float* __restrict__ out,
           int nunits_i) {
    extern __shared__ char smem[];
    const uint32_t sb = smem_u32(smem);
    const int tid  = threadIdx.x;
    const int lane = tid & 31;
    const int warp = tid >> 5;          // 0..15
    const unsigned nunits = (unsigned)nunits_i;

    // ---- one-time cooperative copies ----
    {
        const uint4* s0 = reinterpret_cast<const uint4*>(g_wswz);
        uint4* dW = reinterpret_cast<uint4*>(smem + SM_W);
        #pragma unroll
        for (int i = tid; i < 4096; i += 512) dW[i] = s0[i];
        float* wga_s = reinterpret_cast<float*>(smem + SM_WGA);
        float* wgb_s = reinterpret_cast<float*>(smem + SM_WGB);
        float* ca_s  = reinterpret_cast<float*>(smem + SM_CA);
        float* cb_s  = reinterpret_cast<float*>(smem + SM_CB);
        if (tid < 256) {
            wga_s[tid] = wg_a[tid]; wgb_s[tid] = wg_b[tid];
            ca_s[tid]  = g_c[0][tid]; cb_s[tid] = g_c[1][tid];
        }
    }
    const bool nofold = (g_cflag != 0);
    __syncthreads();

    const int ql = lane & 3;
    const int qr = lane >> 2;
    const char* stage = smem + SM_STAGE + warp * STAGE_WARP;
    const uint32_t stage_u32 = sb + (uint32_t)(SM_STAGE + warp * STAGE_WARP);

    // ---- Wg B-fragments (tile-invariant, f16 pairs) ----
    uint32_t wgA0[4], wgA1[4], wgB0[4], wgB1[4];
    {
        const float* WGAf = reinterpret_cast<const float*>(smem + SM_WGA);
        const float* WGBf = reinterpret_cast<const float*>(smem + SM_WGB);
        const int e4 = qr & 3;
        #pragma unroll
        for (int kt = 0; kt < 4; kt++) {
            int d0 = kt * 16 + 2 * ql;
            wgA0[kt] = pack_h2(WGAf[d0 * 4 + e4],       WGAf[(d0 + 1) * 4 + e4]);
            wgA1[kt] = pack_h2(WGAf[(d0 + 8) * 4 + e4], WGAf[(d0 + 9) * 4 + e4]);
            wgB0[kt] = pack_h2(WGBf[d0 * 4 + e4],       WGBf[(d0 + 1) * 4 + e4]);
            wgB1[kt] = pack_h2(WGBf[(d0 + 8) * 4 + e4], WGBf[(d0 + 9) * 4 + e4]);
        }
    }

    unsigned u = steal(lane);
    if (u < nunits) issue_stage(x, u, stage_u32, lane);

    while (u < nunits) {
        unsigned un = steal(lane);      // pipelined next-unit fetch
        const size_t rowbase = (size_t)u * 32;

        stage_wait();                   // x for unit u ready in smem

        // ---- X fragments from stage (fp32 -> f16 pairs) ----
        uint32_t xf[2][4][4];
        #pragma unroll
        for (int m = 0; m < 2; m++) {
            const char* r0p = stage + (m * 16 + qr) * STAGE_ROW;
            const char* r8p = r0p + 8 * STAGE_ROW;
            #pragma unroll
            for (int kt = 0; kt < 4; kt++) {
                const int cb = (kt * 16 + ql * 2) * 4;
                float2 f0 = *reinterpret_cast<const float2*>(r0p + cb);
                float2 f1 = *reinterpret_cast<const float2*>(r8p + cb);
                float2 f2 = *reinterpret_cast<const float2*>(r0p + cb + 32);
                float2 f3 = *reinterpret_cast<const float2*>(r8p + cb + 32);
                xf[m][kt][0] = pack_h2(f0.x, f0.y);
                xf[m][kt][1] = pack_h2(f1.x, f1.y);
                xf[m][kt][2] = pack_h2(f2.x, f2.y);
                xf[m][kt][3] = pack_h2(f3.x, f3.y);
            }
        }

        // ---- gates A ----
        float4 gAf[2][2];
        uint32_t gA2[4][2][2];
        #pragma unroll
        for (int m = 0; m < 2; m++) {
            uint32_t g2c[4][2];
            gates_core(xf[m], wgA0, wgA1, ql, g2c, nofold ? nullptr : gAf[m]);
            #pragma unroll
            for (int e = 0; e < 4; e++) { gA2[e][m][0] = g2c[e][0]; gA2[e][m][1] = g2c[e][1]; }
        }

        // ---- layer A: f16 acc from zero, GEMM ----
        uint32_t acc[2][8][2];
        #pragma unroll
        for (int n = 0; n < 8; n++)
            #pragma unroll
            for (int m = 0; m < 2; m++) { acc[m][n][0] = 0u; acc[m][n][1] = 0u; }
        run_layer(acc, xf, gA2, sb + SM_W, lane);

        // ---- h -> layer-B A-fragments ----
        if (nofold) {
            // f16 D-fragment layout == A-fragment layout: register renaming.
            #pragma unroll
            for (int m = 0; m < 2; m++)
                #pragma unroll
                for (int kt = 0; kt < 4; kt++) {
                    xf[m][kt][0] = acc[m][2*kt][0];
                    xf[m][kt][1] = acc[m][2*kt][1];
                    xf[m][kt][2] = acc[m][2*kt+1][0];
                    xf[m][kt][3] = acc[m][2*kt+1][1];
                }
        } else {
            // general path: unpack, subtract bias fold in f32, repack
            const float4* CA4 = reinterpret_cast<const float4*>(smem + SM_CA);
            #pragma unroll
            for (int m = 0; m < 2; m++)
                #pragma unroll
                for (int n = 0; n < 8; n++) {
                    int c = n * 8 + ql * 2;
                    float4 c0 = CA4[c], c1 = CA4[c + 1];
                    float2 lo = unpack_h2(acc[m][n][0]);
                    float2 hi = unpack_h2(acc[m][n][1]);
                    lo.x -= dot4(gAf[m][0], c0); lo.y -= dot4(gAf[m][0], c1);
                    hi.x -= dot4(gAf[m][1], c0); hi.y -= dot4(gAf[m][1], c1);
                    int kt = n >> 1, s = n & 1;
                    xf[m][kt][2*s]     = pack_h2(lo.x, lo.y);
                    xf[m][kt][2*s + 1] = pack_h2(hi.x, hi.y);
                }
        }

        // ---- gates B ----
        float4 gBf[2][2];
        uint32_t gB2[4][2][2];
        #pragma unroll
        for (int m = 0; m < 2; m++) {
            uint32_t g2c[4][2];
            gates_core(xf[m], wgB0, wgB1, ql, g2c, nofold ? nullptr : gBf[m]);
            #pragma unroll
            for (int e = 0; e < 4; e++) { gB2[e][m][0] = g2c[e][0]; gB2[e][m][1] = g2c[e][1]; }
        }

        // ---- layer B: f16 acc from zero, GEMM ----
        #pragma unroll
        for (int n = 0; n < 8; n++)
            #pragma unroll
            for (int m = 0; m < 2; m++) { acc[m][n][0] = 0u; acc[m][n][1] = 0u; }
        run_layer(acc, xf, gB2, sb + SM_W + 32768u, lane);

        // ---- epilogue: out = f32(residual from stage) + f32(acc) [- fold] --
        if (nofold) {
            #pragma unroll
            for (int m = 0; m < 2; m++) {
                const size_t rl = rowbase + (size_t)(m * 16 + qr);
                const size_t rh = rl + 8;
                #pragma unroll
                for (int n = 0; n < 8; n++) {
                    int c = n * 8 + ql * 2;
                    const char* rlp = stage + (m * 16 + qr) * STAGE_ROW + c * 4;
                    float2 xl = *reinterpret_cast<const float2*>(rlp);
                    float2 xh = *reinterpret_cast<const float2*>(rlp + 8 * STAGE_ROW);
                    float2 lo = unpack_h2(acc[m][n][0]);
                    float2 hi = unpack_h2(acc[m][n][1]);
                    __stcs(reinterpret_cast<float2*>(out + rl * 64 + c),
                           make_float2(xl.x + lo.x, xl.y + lo.y));
                    __stcs(reinterpret_cast<float2*>(out + rh * 64 + c),
                           make_float2(xh.x + hi.x, xh.y + hi.y));
                }
            }
        } else {
            const float4* CB4 = reinterpret_cast<const float4*>(smem + SM_CB);
            #pragma unroll
            for (int m = 0; m < 2; m++) {
                const size_t rl = rowbase + (size_t)(m * 16 + qr);
                const size_t rh = rl + 8;
                #pragma unroll
                for (int n = 0; n < 8; n++) {
                    int c = n * 8 + ql * 2;
                    float4 c0 = CB4[c], c1 = CB4[c + 1];
                    const char* rlp = stage + (m * 16 + qr) * STAGE_ROW + c * 4;
                    float2 xl = *reinterpret_cast<const float2*>(rlp);
                    float2 xh = *reinterpret_cast<const float2*>(rlp + 8 * STAGE_ROW);
                    float2 lo = unpack_h2(acc[m][n][0]);
                    float2 hi = unpack_h2(acc[m][n][1]);
                    __stcs(reinterpret_cast<float2*>(out + rl * 64 + c),
                           make_float2(xl.x + lo.x - dot4(gBf[m][0], c0),
                                       xl.y + lo.y - dot4(gBf[m][0], c1)));
                    __stcs(reinterpret_cast<float2*>(out + rh * 64 + c),
                           make_float2(xh.x + hi.x - dot4(gBf[m][1], c0),
                                       xh.y + hi.y - dot4(gBf[m][1], c1)));
                }
            }
        }

        // ---- stage consumed: kick off next unit's cp.async ----
        __syncwarp();
        if (un < nunits) issue_stage(x, un, stage_u32, lane);

        u = un;
    }
}

// ------------------------------- launch -----------------------------------

extern "C" void kernel_launch(void* const* d_in, const int* in_sizes, int n_in,
                              void* d_out, int out_size) {
    const float* x   = (const float*)d_in[0];
    const float* wga = (const float*)d_in[1];
    const float* wea = (const float*)d_in[2];
    const float* bea = (const float*)d_in[3];
    const float* wgb = (const float*)d_in[4];
    const float* web = (const float*)d_in[5];
    const float* beb = (const float*)d_in[6];
    float* out = (float*)d_out;

    const int ntok   = in_sizes[0] / 64;
    const int nunits = ntok / 32;

    prep_kernel<<<64, 512>>>(wea, bea, web, beb);

    cudaFuncSetAttribute(moe_kernel, cudaFuncAttributeMaxDynamicSharedMemorySize, SMEM_TOTAL);
    moe_kernel<<<GRID, 512, SMEM_TOTAL>>>(x, wga, wgb, out, nunits);
}